// round 10
// baseline (speedup 1.0000x reference)
#include <cuda_runtime.h>
#include <cuda_bf16.h>

#define W 512
#define H 512
#define TH 32      // output rows per block (even); grid = 1024 blocks
#define EPS 1e-4f

__device__ __forceinline__ float sqrt_approx(float x) {
    float y;
    asm("sqrt.approx.f32 %0, %1;" : "=f"(y) : "f"(x));
    return y;
}

// Issue raw loads for one input row segment.
// Body: one float4. Halo: ONE predicated scalar, active only on warp-edge
// lanes (lane 0 -> left halo, lane 31 -> right halo); interior lanes get
// halos via shuffle at consume time.
__device__ __forceinline__ void fetch_raw(const float* __restrict__ img,
                                          int y, int x0, int lane,
                                          float4& v, float& e) {
    e = 0.f;
    if ((unsigned)y < (unsigned)H) {
        const float* row = img + (size_t)y * W;
        v = *(const float4*)(row + x0);
        if (lane == 0 && x0 > 0)       e = __ldg(row + x0 - 1);
        if (lane == 31 && x0 + 4 < W)  e = __ldg(row + x0 + 4);
    } else {
        v = make_float4(0.f, 0.f, 0.f, 0.f);
    }
}

// Consume a prefetched raw row: resolve halos via intra-warp shuffle (data
// already in registers -> no load coupling), then pre-reduce to
//   d[j] = s[j] - s[j+2]            (horizontal part of gx)
//   t[j] = s[j] + 2*s[j+1] + s[j+2] (horizontal part of gy)
__device__ __forceinline__ void reduce_row(const float4& v, float e, int lane,
                                           float d[4], float t[4]) {
    float l = __shfl_up_sync(0xffffffffu, v.w, 1);
    float r = __shfl_down_sync(0xffffffffu, v.x, 1);
    if (lane == 0)  l = e;
    if (lane == 31) r = e;

    float s0 = l, s1 = v.x, s2 = v.y, s3 = v.z, s4 = v.w, s5 = r;
    d[0] = s0 - s2;
    d[1] = s1 - s3;
    d[2] = s2 - s4;
    d[3] = s3 - s5;
    t[0] = fmaf(2.f, s1, s0 + s2);
    t[1] = fmaf(2.f, s2, s1 + s3);
    t[2] = fmaf(2.f, s3, s2 + s4);
    t[3] = fmaf(2.f, s4, s3 + s5);
}

// gx = (dA + 2 dB + dC)/4, gy = (tA - tC)/4  ->  0.25*sqrt(u^2+v^2+16*eps)
__device__ __forceinline__ float4 magnitude(const float dA[4], const float tA[4],
                                            const float dB[4],
                                            const float dC[4], const float tC[4]) {
    float4 res;
    float u, v;

    u = dA[0] + 2.f * dB[0] + dC[0];
    v = tA[0] - tC[0];
    res.x = 0.25f * sqrt_approx(fmaf(u, u, fmaf(v, v, 16.f * EPS)));

    u = dA[1] + 2.f * dB[1] + dC[1];
    v = tA[1] - tC[1];
    res.y = 0.25f * sqrt_approx(fmaf(u, u, fmaf(v, v, 16.f * EPS)));

    u = dA[2] + 2.f * dB[2] + dC[2];
    v = tA[2] - tC[2];
    res.z = 0.25f * sqrt_approx(fmaf(u, u, fmaf(v, v, 16.f * EPS)));

    u = dA[3] + 2.f * dB[3] + dC[3];
    v = tA[3] - tC[3];
    res.w = 0.25f * sqrt_approx(fmaf(u, u, fmaf(v, v, 16.f * EPS)));
    return res;
}

__global__ __launch_bounds__(128, 8) void sobel_kernel(const float* __restrict__ in,
                                                       float* __restrict__ out) {
    const int b    = blockIdx.z;
    const int lane = threadIdx.x & 31;
    const int x0   = threadIdx.x * 4;        // 128 threads * 4 cols = 512 = W
    const int y0   = blockIdx.y * TH;

    const float* img = in  + (size_t)b * H * W;
    float*       o   = out + (size_t)b * H * W;

    // Reduced rolling-window rows
    float dA[4], tA[4], dB[4], tB[4], dC[4], tC[4], dD[4], tD[4];

    // Prefetched raw rows for the NEXT iteration (software pipeline, depth 1)
    float4 p0v, p1v;
    float  p0e, p1e;

    {
        float4 vA, vB; float eA, eB;
        fetch_raw(img, y0 - 1, x0, lane, vA, eA);   // independent loads,
        fetch_raw(img, y0,     x0, lane, vB, eB);   // batched up front
        fetch_raw(img, y0 + 1, x0, lane, p0v, p0e);
        fetch_raw(img, y0 + 2, x0, lane, p1v, p1e);
        reduce_row(vA, eA, lane, dA, tA);
        reduce_row(vB, eB, lane, dB, tB);
    }

#pragma unroll
    for (int i = 0; i < TH / 2; i++) {
        const int y = y0 + 2 * i;

        // 1) Issue next iteration's loads FIRST (overlap with this iter's compute)
        float4 n0v, n1v;
        float  n0e, n1e;
        if (i < TH / 2 - 1) {                 // compile-time under full unroll
            fetch_raw(img, y + 3, x0, lane, n0v, n0e);
            fetch_raw(img, y + 4, x0, lane, n1v, n1e);
        }

        // 2) Consume rows prefetched one iteration ago (shuffles touch only
        //    already-landed registers)
        reduce_row(p0v, p0e, lane, dC, tC);   // row y+1
        reduce_row(p1v, p1e, lane, dD, tD);   // row y+2

        // Two independent magnitude chains (ILP)
        float4 r0 = magnitude(dA, tA, dB, dC, tC);   // row y
        float4 r1 = magnitude(dB, tB, dC, dD, tD);   // row y+1

        __stcs((float4*)(o + (size_t)y       * W + x0), r0);
        __stcs((float4*)(o + (size_t)(y + 1) * W + x0), r1);

        // 3) Rotate window + pipeline regs (full unroll -> renaming)
#pragma unroll
        for (int j = 0; j < 4; j++) {
            dA[j] = dC[j]; tA[j] = tC[j];
            dB[j] = dD[j]; tB[j] = tD[j];
        }
        if (i < TH / 2 - 1) {
            p0v = n0v; p0e = n0e;
            p1v = n1v; p1e = n1e;
        }
    }
}

extern "C" void kernel_launch(void* const* d_in, const int* in_sizes, int n_in,
                              void* d_out, int out_size) {
    const float* x = (const float*)d_in[0];
    float* out = (float*)d_out;

    const int total = in_sizes[0];          // B * 1 * H * W
    const int B = total / (H * W);

    dim3 block(128, 1, 1);
    dim3 grid(1, H / TH, B);
    sobel_kernel<<<grid, block>>>(x, out);
}

// round 11
// speedup vs baseline: 1.0556x; 1.0556x over previous
#include <cuda_runtime.h>
#include <cuda_bf16.h>

#define W 512
#define H 512
#define TH 16        // output rows per block; grid = 2048 blocks
#define EPS 1e-4f
#define NSLOT 8      // smem ring slots (power of 2)
#define DEPTH 6      // rows prefetched ahead (pipeline depth)
#define PITCH 520    // floats per slot row (16B-multiple: keeps float4 alignment)

__device__ __forceinline__ float sqrt_approx(float x) {
    float y;
    asm("sqrt.approx.f32 %0, %1;" : "=f"(y) : "f"(x));
    return y;
}

__device__ __forceinline__ void cp_async16(float* dst, const float* src) {
    unsigned sa = (unsigned)__cvta_generic_to_shared(dst);
    asm volatile("cp.async.cg.shared.global [%0], [%1], 16;" :: "r"(sa), "l"(src));
}

// Slot layout: [3] = left halo (always 0), data cols 0..511 at [4..515],
// [516] = right halo (always 0). cp.async dst (index 4+4*tid) is 16B aligned.
__device__ __forceinline__ void stage_row(float* slot, const float* __restrict__ img,
                                          int r, int c0) {
    float* dst = slot + 4 + c0;
    if ((unsigned)r < (unsigned)H) {
        cp_async16(dst, img + (size_t)r * W + c0);
    } else {
        *(float4*)dst = make_float4(0.f, 0.f, 0.f, 0.f);   // zero pad row
    }
    asm volatile("cp.async.commit_group;");
}

// Read one staged row from smem and pre-reduce to
//   d[j] = s[j] - s[j+2]            (horizontal part of gx)
//   t[j] = s[j] + 2*s[j+1] + s[j+2] (horizontal part of gy)
__device__ __forceinline__ void reduce_slot(const float* slot, int c0,
                                            float d[4], float t[4]) {
    float4 v = *(const float4*)(slot + 4 + c0);
    float l = slot[3 + c0];
    float r = slot[8 + c0];

    float s0 = l, s1 = v.x, s2 = v.y, s3 = v.z, s4 = v.w, s5 = r;
    d[0] = s0 - s2;
    d[1] = s1 - s3;
    d[2] = s2 - s4;
    d[3] = s3 - s5;
    t[0] = fmaf(2.f, s1, s0 + s2);
    t[1] = fmaf(2.f, s2, s1 + s3);
    t[2] = fmaf(2.f, s3, s2 + s4);
    t[3] = fmaf(2.f, s4, s3 + s5);
}

// gx = (dA + 2 dB + dC)/4, gy = (tA - tC)/4  ->  0.25*sqrt(u^2+v^2+16*eps)
__device__ __forceinline__ float4 magnitude(const float dA[4], const float tA[4],
                                            const float dB[4],
                                            const float dC[4], const float tC[4]) {
    float4 res;
    float u, v;

    u = dA[0] + 2.f * dB[0] + dC[0];
    v = tA[0] - tC[0];
    res.x = 0.25f * sqrt_approx(fmaf(u, u, fmaf(v, v, 16.f * EPS)));

    u = dA[1] + 2.f * dB[1] + dC[1];
    v = tA[1] - tC[1];
    res.y = 0.25f * sqrt_approx(fmaf(u, u, fmaf(v, v, 16.f * EPS)));

    u = dA[2] + 2.f * dB[2] + dC[2];
    v = tA[2] - tC[2];
    res.z = 0.25f * sqrt_approx(fmaf(u, u, fmaf(v, v, 16.f * EPS)));

    u = dA[3] + 2.f * dB[3] + dC[3];
    v = tA[3] - tC[3];
    res.w = 0.25f * sqrt_approx(fmaf(u, u, fmaf(v, v, 16.f * EPS)));
    return res;
}

__global__ __launch_bounds__(128, 10) void sobel_kernel(const float* __restrict__ in,
                                                        float* __restrict__ out) {
    __shared__ float ring[NSLOT][PITCH];     // 8 * 520 * 4 = 16640 B

    const int tid = threadIdx.x;
    const int b   = blockIdx.z;
    const int y0  = blockIdx.y * TH;
    const int c0  = tid * 4;                 // 128 threads * 4 cols = 512 = W

    const float* img = in  + (size_t)b * H * W;
    float*       o   = out + (size_t)b * H * W;

    // One-time halo zeros (slots are reused; halo words never overwritten)
    if (tid < NSLOT) {
        ring[tid][3]   = 0.f;
        ring[tid][516] = 0.f;
    }

    // Prologue: stage rows k = 0..DEPTH-1  (global rows y0-1 .. y0+DEPTH-2)
#pragma unroll
    for (int k = 0; k < DEPTH; k++)
        stage_row(ring[k], img, y0 - 1 + k, c0);

    float dA[4], tA[4], dB[4], tB[4], dC[4], tC[4];

    // Need rows k=0,1 (y0-1, y0): groups 1,2 complete  -> <=4 pending
    asm volatile("cp.async.wait_group 4;");
    __syncthreads();
    reduce_slot(ring[0], c0, dA, tA);
    reduce_slot(ring[1], c0, dB, tB);

#pragma unroll
    for (int i = 0; i < TH; i++) {
        const int y = y0 + i;

        // Wait until row k=i+2 has landed (group i+3 complete).
        if (i < TH - 3)       asm volatile("cp.async.wait_group 3;");
        else if (i == TH - 3) asm volatile("cp.async.wait_group 2;");
        else if (i == TH - 2) asm volatile("cp.async.wait_group 1;");
        else                  asm volatile("cp.async.wait_group 0;");
        __syncthreads();

        // Consume newly landed row y+1 (slot k=i+2)
        reduce_slot(ring[(i + 2) % NSLOT], c0, dC, tC);

        float4 res = magnitude(dA, tA, dB, dC, tC);
        __stcs((float4*)(o + (size_t)y * W + c0), res);

        // Issue load for row k = DEPTH+i (global row y0-1+DEPTH+i), 3 ahead.
        // Overwrites slot (i+6)%8; current readers touch i..i+2 -> disjoint.
        if (i < TH + 2 - DEPTH)
            stage_row(ring[(DEPTH + i) % NSLOT], img, y0 - 1 + DEPTH + i, c0);

        // Roll the reduced window (full unroll -> register renaming)
#pragma unroll
        for (int j = 0; j < 4; j++) {
            dA[j] = dB[j]; tA[j] = tB[j];
            dB[j] = dC[j]; tB[j] = tC[j];
        }
    }
}

extern "C" void kernel_launch(void* const* d_in, const int* in_sizes, int n_in,
                              void* d_out, int out_size) {
    const float* x = (const float*)d_in[0];
    float* out = (float*)d_out;

    const int total = in_sizes[0];          // B * 1 * H * W
    const int B = total / (H * W);

    dim3 block(128, 1, 1);
    dim3 grid(1, H / TH, B);
    sobel_kernel<<<grid, block>>>(x, out);
}